// round 6
// baseline (speedup 1.0000x reference)
#include <cuda_runtime.h>
#include <cuda_fp16.h>
#include <math.h>

#define CC   256
#define CQ   32
#define NPIX 4096
#define EPSB 1e-5f
#define KW   2304          // 9*256 conv K

// smem row pads (u32 elems) chosen for conflict-free fragment LDS
#define PA 36              // A tiles [m][k]
#define PB 136             // B tiles [k][n]
#define PQ 68              // q tile [c][m]
#define PH 20              // half2 tiles [row][16 h2] padded

// ---------------- scratch ----------------
__device__ float g_xf1[CC * NPIX];
__device__ float g_xf2[CC * NPIX];
__device__ float g_qb1[CQ * NPIX];
__device__ float g_kb1[CQ * NPIX];
__device__ float g_vb1[CC * NPIX];
__device__ float g_qb2[CQ * NPIX];
__device__ float g_kb2[CQ * NPIX];
__device__ float g_vb2[CC * NPIX];
__device__ float g_attn1[(size_t)NPIX * NPIX];
__device__ float g_attn2[(size_t)NPIX * NPIX];
__device__ __half g_p1[(size_t)NPIX * NPIX];    // normalized attn, fp16
__device__ __half g_p2[(size_t)NPIX * NPIX];
__device__ float g_wx1p[CC * KW];
__device__ float g_wy1p[CC * KW];
__device__ float g_wx2p[CC * KW];
__device__ float g_wy2p[CC * KW];

// ---------------- mma helpers ----------------
__device__ __forceinline__ unsigned f2tf32(float x) {
    unsigned r; asm("cvt.rna.tf32.f32 %0, %1;" : "=r"(r) : "f"(x)); return r;
}
__device__ __forceinline__ void mma8(float* c, const unsigned* a, const unsigned* b) {
    asm volatile(
        "mma.sync.aligned.m16n8k8.row.col.f32.tf32.tf32.f32 "
        "{%0,%1,%2,%3}, {%4,%5,%6,%7}, {%8,%9}, {%0,%1,%2,%3};"
        : "+f"(c[0]), "+f"(c[1]), "+f"(c[2]), "+f"(c[3])
        : "r"(a[0]), "r"(a[1]), "r"(a[2]), "r"(a[3]), "r"(b[0]), "r"(b[1]));
}
__device__ __forceinline__ void mma16h(float* c, const unsigned* a, const unsigned* b) {
    asm volatile(
        "mma.sync.aligned.m16n8k16.row.col.f32.f16.f16.f32 "
        "{%0,%1,%2,%3}, {%4,%5,%6,%7}, {%8,%9}, {%0,%1,%2,%3};"
        : "+f"(c[0]), "+f"(c[1]), "+f"(c[2]), "+f"(c[3])
        : "r"(a[0]), "r"(a[1]), "r"(a[2]), "r"(a[3]), "r"(b[0]), "r"(b[1]));
}
__device__ __forceinline__ unsigned h2u(float lo, float hi) {
    __half2 h = __floats2half2_rn(lo, hi);
    return *reinterpret_cast<unsigned*>(&h);
}

// ---------------------------------------------------------------------------
// pack all 4 conv-weight tensors: w[m][ci][tap] -> wp[m][tap*256+ci]
// ---------------------------------------------------------------------------
__global__ void pack_all(const float* __restrict__ s0, const float* __restrict__ s1,
                         const float* __restrict__ s2, const float* __restrict__ s3,
                         float* __restrict__ d0, float* __restrict__ d1,
                         float* __restrict__ d2, float* __restrict__ d3)
{
    const int y = blockIdx.y;
    const float* s = (y == 0) ? s0 : (y == 1) ? s1 : (y == 2) ? s2 : s3;
    float* d = (y == 0) ? d0 : (y == 1) ? d1 : (y == 2) ? d2 : d3;
    int t = blockIdx.x * 256 + threadIdx.x;
    int m = t / KW, r = t % KW;
    d[t] = s[m * KW + (r & 255) * 9 + (r >> 8)];
}

// ---------------------------------------------------------------------------
// Sobel (batched z=2): dual conv3x3 GEMM + BN + magnitude, double-buffered.
// grid (32, 4, 2), block 256, dynamic smem.
// ---------------------------------------------------------------------------
__global__ void sobel_mma(const float* __restrict__ x1a, const float* __restrict__ wx1,
                          const float* __restrict__ wy1, const float* __restrict__ bn1x,
                          const float* __restrict__ bn1y, float* __restrict__ o1,
                          const float* __restrict__ x2a, const float* __restrict__ wx2,
                          const float* __restrict__ wy2, const float* __restrict__ bn2x,
                          const float* __restrict__ bn2y, float* __restrict__ o2)
{
    extern __shared__ unsigned sh[];
    unsigned* AxB = sh;
    unsigned* AyB = sh + 2 * 64 * PA;
    unsigned* BsB = sh + 4 * 64 * PA;

    const int z = blockIdx.z;
    const float* x   = z ? x2a : x1a;
    const float* wxp = z ? wx2 : wx1;
    const float* wyp = z ? wy2 : wy1;
    const float* bnx = z ? bn2x : bn1x;
    const float* bny = z ? bn2y : bn1y;
    float* out = z ? o2 : o1;

    const int tid = threadIdx.x;
    const int lane = tid & 31, wid = tid >> 5;
    const int g = lane >> 2, tig = lane & 3;
    const int m_off = (wid >> 2) * 32, n_off = (wid & 3) * 32;
    const int m0 = blockIdx.y * 64, n0 = blockIdx.x * 128;

    float accx[2][4][4] = {};
    float accy[2][4][4] = {};

    float4 rAx[2], rAy[2];
    float rB[4][4];

    const int amr = tid >> 3, ac4 = (tid & 7) * 4;
    const int bkl = tid >> 5, bc4 = (tid & 31) * 4;

    #define S_LOAD_A(kt) { \
        rAx[0] = *(const float4*)&wxp[(m0 + amr) * KW + (kt) + ac4]; \
        rAy[0] = *(const float4*)&wyp[(m0 + amr) * KW + (kt) + ac4]; \
        rAx[1] = *(const float4*)&wxp[(m0 + amr + 32) * KW + (kt) + ac4]; \
        rAy[1] = *(const float4*)&wyp[(m0 + amr + 32) * KW + (kt) + ac4]; }

    #define S_LOAD_B(kt) { \
        const int tap = (kt) >> 8; \
        const int dy = tap / 3 - 1, dx = tap % 3 - 1; \
        const int cibase = (kt) & 255; \
        _Pragma("unroll") \
        for (int r = 0; r < 4; r++) { \
            int ci = cibase + bkl + r * 8; \
            _Pragma("unroll") \
            for (int j = 0; j < 4; j++) { \
                int pix = n0 + bc4 + j; \
                int yy = (pix >> 6) + dy; \
                int xx = (pix & 63) + dx; \
                float f = 0.f; \
                if (yy >= 0 && yy < 64 && xx >= 0 && xx < 64) \
                    f = x[ci * NPIX + yy * 64 + xx]; \
                rB[r][j] = f; \
            } \
        } }

    #define S_STORE(buf) { \
        unsigned* Ax = AxB + (buf) * 64 * PA; \
        unsigned* Ay = AyB + (buf) * 64 * PA; \
        unsigned* Bs = BsB + (buf) * 32 * PB; \
        unsigned* p0 = &Ax[amr * PA + ac4]; \
        p0[0]=f2tf32(rAx[0].x); p0[1]=f2tf32(rAx[0].y); p0[2]=f2tf32(rAx[0].z); p0[3]=f2tf32(rAx[0].w); \
        unsigned* p1 = &Ax[(amr + 32) * PA + ac4]; \
        p1[0]=f2tf32(rAx[1].x); p1[1]=f2tf32(rAx[1].y); p1[2]=f2tf32(rAx[1].z); p1[3]=f2tf32(rAx[1].w); \
        unsigned* p2 = &Ay[amr * PA + ac4]; \
        p2[0]=f2tf32(rAy[0].x); p2[1]=f2tf32(rAy[0].y); p2[2]=f2tf32(rAy[0].z); p2[3]=f2tf32(rAy[0].w); \
        unsigned* p3 = &Ay[(amr + 32) * PA + ac4]; \
        p3[0]=f2tf32(rAy[1].x); p3[1]=f2tf32(rAy[1].y); p3[2]=f2tf32(rAy[1].z); p3[3]=f2tf32(rAy[1].w); \
        _Pragma("unroll") \
        for (int r = 0; r < 4; r++) { \
            unsigned* bp = &Bs[(bkl + r * 8) * PB + bc4]; \
            bp[0]=f2tf32(rB[r][0]); bp[1]=f2tf32(rB[r][1]); bp[2]=f2tf32(rB[r][2]); bp[3]=f2tf32(rB[r][3]); \
        } }

    S_LOAD_A(0); S_LOAD_B(0);
    S_STORE(0);
    __syncthreads();

    int buf = 0;
    for (int c = 0; c < KW / 32; c++) {
        const bool more = (c + 1 < KW / 32);
        if (more) { const int ktn = (c + 1) * 32; S_LOAD_A(ktn); S_LOAD_B(ktn); }

        const unsigned* Ax = AxB + buf * 64 * PA;
        const unsigned* Ay = AyB + buf * 64 * PA;
        const unsigned* Bs = BsB + buf * 32 * PB;
        #pragma unroll
        for (int ks = 0; ks < 4; ks++) {
            const int k0 = ks * 8;
            unsigned ax[2][4], ay[2][4], b[4][2];
            #pragma unroll
            for (int mf = 0; mf < 2; mf++) {
                int mr = m_off + mf * 16 + g;
                ax[mf][0] = Ax[mr * PA + k0 + tig];
                ax[mf][1] = Ax[(mr + 8) * PA + k0 + tig];
                ax[mf][2] = Ax[mr * PA + k0 + tig + 4];
                ax[mf][3] = Ax[(mr + 8) * PA + k0 + tig + 4];
                ay[mf][0] = Ay[mr * PA + k0 + tig];
                ay[mf][1] = Ay[(mr + 8) * PA + k0 + tig];
                ay[mf][2] = Ay[mr * PA + k0 + tig + 4];
                ay[mf][3] = Ay[(mr + 8) * PA + k0 + tig + 4];
            }
            #pragma unroll
            for (int nf = 0; nf < 4; nf++) {
                int nc = n_off + nf * 8 + g;
                b[nf][0] = Bs[(k0 + tig) * PB + nc];
                b[nf][1] = Bs[(k0 + tig + 4) * PB + nc];
            }
            #pragma unroll
            for (int mf = 0; mf < 2; mf++)
                #pragma unroll
                for (int nf = 0; nf < 4; nf++) {
                    mma8(accx[mf][nf], ax[mf], b[nf]);
                    mma8(accy[mf][nf], ay[mf], b[nf]);
                }
        }
        if (more) S_STORE(buf ^ 1);
        __syncthreads();
        buf ^= 1;
    }

    #pragma unroll
    for (int mf = 0; mf < 2; mf++) {
        int r0 = m0 + m_off + mf * 16 + g;
        int r1 = r0 + 8;
        float ivx0 = bnx[r0] * rsqrtf(bnx[768 + r0] + EPSB);
        float ivx1 = bnx[r1] * rsqrtf(bnx[768 + r1] + EPSB);
        float bx0 = bnx[256 + r0], bx1 = bnx[256 + r1];
        float mx0 = bnx[512 + r0], mx1 = bnx[512 + r1];
        float ivy0 = bny[r0] * rsqrtf(bny[768 + r0] + EPSB);
        float ivy1 = bny[r1] * rsqrtf(bny[768 + r1] + EPSB);
        float by0 = bny[256 + r0], by1 = bny[256 + r1];
        float my0 = bny[512 + r0], my1 = bny[512 + r1];
        #pragma unroll
        for (int nf = 0; nf < 4; nf++) {
            int col = n0 + n_off + nf * 8 + 2 * tig;
            float gx, gy;
            float2 o0, o1;
            gx = (accx[mf][nf][0] - mx0) * ivx0 + bx0;
            gy = (accy[mf][nf][0] - my0) * ivy0 + by0;
            o0.x = sqrtf(gx * gx + gy * gy);
            gx = (accx[mf][nf][1] - mx0) * ivx0 + bx0;
            gy = (accy[mf][nf][1] - my0) * ivy0 + by0;
            o0.y = sqrtf(gx * gx + gy * gy);
            gx = (accx[mf][nf][2] - mx1) * ivx1 + bx1;
            gy = (accy[mf][nf][2] - my1) * ivy1 + by1;
            o1.x = sqrtf(gx * gx + gy * gy);
            gx = (accx[mf][nf][3] - mx1) * ivx1 + bx1;
            gy = (accy[mf][nf][3] - my1) * ivy1 + by1;
            o1.y = sqrtf(gx * gx + gy * gy);
            *(float2*)&out[r0 * NPIX + col] = o0;
            *(float2*)&out[r1 * NPIX + col] = o1;
        }
    }
}

// ---------------------------------------------------------------------------
// proj (batched): out[M][4096] = W[M][256] * B + bias. z selects arg set.
// ---------------------------------------------------------------------------
struct ProjArgs {
    const float* A[4];
    const float* B[4];
    const float* bias[4];
    float* out[4];
    int M;
};

__global__ void __launch_bounds__(256, 2) proj_mma(ProjArgs args)
{
    extern __shared__ unsigned sh[];
    unsigned* AsB = sh;
    unsigned* BsB = sh + 2 * 64 * PA;

    const int z = blockIdx.z;
    const float* A = args.A[z];
    const float* B = args.B[z];
    const float* bias = args.bias[z];
    float* out = args.out[z];
    const int M = args.M;

    const int tid = threadIdx.x;
    const int lane = tid & 31, wid = tid >> 5;
    const int g = lane >> 2, tig = lane & 3;
    const int m_off = (wid >> 2) * 32, n_off = (wid & 3) * 32;
    const int m0 = blockIdx.y * 64, n0 = blockIdx.x * 128;

    float acc[2][4][4] = {};
    float4 rA[2], rB[4];

    const int amr = tid >> 3, ac4 = (tid & 7) * 4;
    const int bkl = tid >> 5, bc4 = (tid & 31) * 4;

    #define P_LOAD(kt) { \
        rA[0] = (m0 + amr < M) ? *(const float4*)&A[(m0 + amr) * 256 + (kt) + ac4] \
                               : make_float4(0.f, 0.f, 0.f, 0.f); \
        rA[1] = (m0 + amr + 32 < M) ? *(const float4*)&A[(m0 + amr + 32) * 256 + (kt) + ac4] \
                                    : make_float4(0.f, 0.f, 0.f, 0.f); \
        _Pragma("unroll") \
        for (int r = 0; r < 4; r++) \
            rB[r] = *(const float4*)&B[((kt) + bkl + r * 8) * NPIX + n0 + bc4]; }

    #define P_STORE(buf) { \
        unsigned* As = AsB + (buf) * 64 * PA; \
        unsigned* Bs = BsB + (buf) * 32 * PB; \
        unsigned* p0 = &As[amr * PA + ac4]; \
        p0[0]=f2tf32(rA[0].x); p0[1]=f2tf32(rA[0].y); p0[2]=f2tf32(rA[0].z); p0[3]=f2tf32(rA[0].w); \
        unsigned* p1 = &As[(amr + 32) * PA + ac4]; \
        p1[0]=f2tf32(rA[1].x); p1[1]=f2tf32(rA[1].y); p1[2]=f2tf32(rA[1].z); p1[3]=f2tf32(rA[1].w); \
        _Pragma("unroll") \
        for (int r = 0; r < 4; r++) { \
            unsigned* bp = &Bs[(bkl + r * 8) * PB + bc4]; \
            bp[0]=f2tf32(rB[r].x); bp[1]=f2tf32(rB[r].y); bp[2]=f2tf32(rB[r].z); bp[3]=f2tf32(rB[r].w); \
        } }

    P_LOAD(0);
    P_STORE(0);
    __syncthreads();

    int buf = 0;
    for (int c = 0; c < 8; c++) {
        const bool more = (c + 1 < 8);
        if (more) { const int ktn = (c + 1) * 32; P_LOAD(ktn); }

        const unsigned* As = AsB + buf * 64 * PA;
        const unsigned* Bs = BsB + buf * 32 * PB;
        #pragma unroll
        for (int ks = 0; ks < 4; ks++) {
            const int k0 = ks * 8;
            unsigned a[2][4], b[4][2];
            #pragma unroll
            for (int mf = 0; mf < 2; mf++) {
                int mr = m_off + mf * 16 + g;
                a[mf][0] = As[mr * PA + k0 + tig];
                a[mf][1] = As[(mr + 8) * PA + k0 + tig];
                a[mf][2] = As[mr * PA + k0 + tig + 4];
                a[mf][3] = As[(mr + 8) * PA + k0 + tig + 4];
            }
            #pragma unroll
            for (int nf = 0; nf < 4; nf++) {
                int nc = n_off + nf * 8 + g;
                b[nf][0] = Bs[(k0 + tig) * PB + nc];
                b[nf][1] = Bs[(k0 + tig + 4) * PB + nc];
            }
            #pragma unroll
            for (int mf = 0; mf < 2; mf++)
                #pragma unroll
                for (int nf = 0; nf < 4; nf++)
                    mma8(acc[mf][nf], a[mf], b[nf]);
        }
        if (more) P_STORE(buf ^ 1);
        __syncthreads();
        buf ^= 1;
    }

    #pragma unroll
    for (int mf = 0; mf < 2; mf++) {
        int r0 = m0 + m_off + mf * 16 + g;
        int r1 = r0 + 8;
        float b0 = (r0 < M) ? bias[r0] : 0.f;
        float b1 = (r1 < M) ? bias[r1] : 0.f;
        #pragma unroll
        for (int nf = 0; nf < 4; nf++) {
            int col = n0 + n_off + nf * 8 + 2 * tig;
            if (r0 < M)
                *(float2*)&out[r0 * NPIX + col] =
                    make_float2(acc[mf][nf][0] + b0, acc[mf][nf][1] + b0);
            if (r1 < M)
                *(float2*)&out[r1 * NPIX + col] =
                    make_float2(acc[mf][nf][2] + b1, acc[mf][nf][3] + b1);
        }
    }
}

// ---------------------------------------------------------------------------
// energy (batched z=2). grid (32, 64, 2), block 256.
// ---------------------------------------------------------------------------
__global__ void energy_mma(const float* __restrict__ q1, const float* __restrict__ k1,
                           float* __restrict__ e1,
                           const float* __restrict__ q2, const float* __restrict__ k2,
                           float* __restrict__ e2)
{
    __shared__ unsigned Qs[32 * PQ];
    __shared__ unsigned Ks[32 * PB];

    const int z = blockIdx.z;
    const float* q = z ? q2 : q1;
    const float* k = z ? k2 : k1;
    float* e = z ? e2 : e1;

    const int tid = threadIdx.x;
    const int lane = tid & 31, wid = tid >> 5;
    const int g = lane >> 2, tig = lane & 3;
    const int m_off = (wid >> 2) * 32, n_off = (wid & 3) * 32;
    const int m0 = blockIdx.y * 64, n0 = blockIdx.x * 128;

    #pragma unroll
    for (int r = 0; r < 2; r++) {
        int idx = tid + r * 256;
        int c = idx >> 4, m4 = (idx & 15) * 4;
        float4 v = *(const float4*)&q[c * NPIX + m0 + m4];
        unsigned* p = &Qs[c * PQ + m4];
        p[0] = f2tf32(v.x); p[1] = f2tf32(v.y); p[2] = f2tf32(v.z); p[3] = f2tf32(v.w);
    }
    #pragma unroll
    for (int r = 0; r < 4; r++) {
        int idx = tid + r * 256;
        int c = idx >> 5, c4 = (idx & 31) * 4;
        float4 v = *(const float4*)&k[c * NPIX + n0 + c4];
        unsigned* p = &Ks[c * PB + c4];
        p[0] = f2tf32(v.x); p[1] = f2tf32(v.y); p[2] = f2tf32(v.z); p[3] = f2tf32(v.w);
    }
    __syncthreads();

    float acc[2][4][4] = {};
    #pragma unroll
    for (int ks = 0; ks < 4; ks++) {
        const int k0 = ks * 8;
        unsigned a[2][4], b[4][2];
        #pragma unroll
        for (int mf = 0; mf < 2; mf++) {
            int mr = m_off + mf * 16 + g;
            a[mf][0] = Qs[(k0 + tig) * PQ + mr];
            a[mf][1] = Qs[(k0 + tig) * PQ + mr + 8];
            a[mf][2] = Qs[(k0 + tig + 4) * PQ + mr];
            a[mf][3] = Qs[(k0 + tig + 4) * PQ + mr + 8];
        }
        #pragma unroll
        for (int nf = 0; nf < 4; nf++) {
            int nc = n_off + nf * 8 + g;
            b[nf][0] = Ks[(k0 + tig) * PB + nc];
            b[nf][1] = Ks[(k0 + tig + 4) * PB + nc];
        }
        #pragma unroll
        for (int mf = 0; mf < 2; mf++)
            #pragma unroll
            for (int nf = 0; nf < 4; nf++)
                mma8(acc[mf][nf], a[mf], b[nf]);
    }

    #pragma unroll
    for (int mf = 0; mf < 2; mf++) {
        int r0 = m0 + m_off + mf * 16 + g;
        int r1 = r0 + 8;
        #pragma unroll
        for (int nf = 0; nf < 4; nf++) {
            int col = n0 + n_off + nf * 8 + 2 * tig;
            *(float2*)&e[(size_t)r0 * NPIX + col] = make_float2(acc[mf][nf][0], acc[mf][nf][1]);
            *(float2*)&e[(size_t)r1 * NPIX + col] = make_float2(acc[mf][nf][2], acc[mf][nf][3]);
        }
    }
}

// ---------------------------------------------------------------------------
// softmax (batched z=2): read fp32 E rows, write normalized fp16 P rows.
// grid (4096, 2), block 256.
// ---------------------------------------------------------------------------
__global__ void softmax_kernel(const float* __restrict__ e1, const float* __restrict__ e2,
                               __half* __restrict__ p1, __half* __restrict__ p2)
{
    __shared__ float red[8];
    const float* e = blockIdx.y ? e2 : e1;
    __half* po = blockIdx.y ? p2 : p1;
    const float4* p = (const float4*)(e + (size_t)blockIdx.x * NPIX);
    __half2* ph = (__half2*)(po + (size_t)blockIdx.x * NPIX);
    const int tid = threadIdx.x;
    float4 v[4];
    float mx = -1e30f;
    #pragma unroll
    for (int r = 0; r < 4; r++) {
        v[r] = p[tid + r * 256];
        mx = fmaxf(mx, fmaxf(fmaxf(v[r].x, v[r].y), fmaxf(v[r].z, v[r].w)));
    }
    #pragma unroll
    for (int o = 16; o > 0; o >>= 1)
        mx = fmaxf(mx, __shfl_xor_sync(0xffffffffu, mx, o));
    if ((tid & 31) == 0) red[tid >> 5] = mx;
    __syncthreads();
    mx = red[0];
    #pragma unroll
    for (int w = 1; w < 8; w++) mx = fmaxf(mx, red[w]);
    __syncthreads();

    float s = 0.f;
    #pragma unroll
    for (int r = 0; r < 4; r++) {
        v[r].x = __expf(v[r].x - mx); s += v[r].x;
        v[r].y = __expf(v[r].y - mx); s += v[r].y;
        v[r].z = __expf(v[r].z - mx); s += v[r].z;
        v[r].w = __expf(v[r].w - mx); s += v[r].w;
    }
    #pragma unroll
    for (int o = 16; o > 0; o >>= 1)
        s += __shfl_xor_sync(0xffffffffu, s, o);
    if ((tid & 31) == 0) red[tid >> 5] = s;
    __syncthreads();
    s = 0.f;
    #pragma unroll
    for (int w = 0; w < 8; w++) s += red[w];
    const float inv = 1.f / s;
    #pragma unroll
    for (int r = 0; r < 4; r++) {
        int i2 = (tid + r * 256) * 2;
        ph[i2]     = __floats2half2_rn(v[r].x * inv, v[r].y * inv);
        ph[i2 + 1] = __floats2half2_rn(v[r].z * inv, v[r].w * inv);
    }
}

// ---------------------------------------------------------------------------
// av fp16 (batched z=2): out[m][n] = gamma * sum_k V[m][k] * P[n][k] + xq[m][n]
// m-tile 128, n-tile 128, k-tile 32. grid (32, 2, 2), block 256 (4x2 warps).
// V fp32 -> fp16 at smem store; P read fp16 from global. Double-buffered.
// ---------------------------------------------------------------------------
__global__ void __launch_bounds__(256, 1) av_fp16(
    const float* __restrict__ v1, const __half* __restrict__ p1,
    const float* __restrict__ xq1, const float* __restrict__ gm1,
    const float* __restrict__ v2, const __half* __restrict__ p2,
    const float* __restrict__ xq2, const float* __restrict__ gm2,
    float* __restrict__ outbase)
{
    __shared__ unsigned Vs[2][128 * PH];   // half2 pairs along k: [row][k/2]
    __shared__ unsigned Ps[2][128 * PH];

    const int z = blockIdx.z;
    const float* vmat = z ? v2 : v1;
    const __half* pm  = z ? p2 : p1;
    const float* xq   = z ? xq2 : xq1;
    const float* gmp  = z ? gm2 : gm1;
    float* out = outbase + (size_t)z * CC * NPIX;

    const int tid = threadIdx.x;
    const int lane = tid & 31, wid = tid >> 5;
    const int g = lane >> 2, tig = lane & 3;
    const int m_off = (wid >> 1) * 32;       // 4 warp rows
    const int n_off = (wid & 1) * 64;        // 2 warp cols
    const int m0 = blockIdx.y * 128, n0 = blockIdx.x * 128;

    float acc[2][8][4] = {};

    // cooperative-load indices
    const int vrow = tid >> 1, vc8 = (tid & 1) * 16;   // V: 2 threads/row, 16 floats each
    const int prow = tid >> 1, pc4 = (tid & 1) * 8;    // P: 2 threads/row, 8 u32 each

    float4 rV[4];
    uint4 rP[2];

    #define AV_LOAD(kt) { \
        _Pragma("unroll") \
        for (int r = 0; r < 4; r++) \
            rV[r] = *(const float4*)&vmat[(m0 + vrow) * NPIX + (kt) + vc8 + r * 4]; \
        const unsigned* pu = (const unsigned*)(pm + (size_t)(n0 + prow) * NPIX + (kt)); \
        rP[0] = *(const uint4*)&pu[pc4]; \
        rP[1] = *(const uint4*)&pu[pc4 + 4]; }

    #define AV_STORE(buf) { \
        unsigned* vp = &Vs[buf][vrow * PH + vc8 / 2]; \
        vp[0] = h2u(rV[0].x, rV[0].y); vp[1] = h2u(rV[0].z, rV[0].w); \
        vp[2] = h2u(rV[1].x, rV[1].y); vp[3] = h2u(rV[1].z, rV[1].w); \
        vp[4] = h2u(rV[2].x, rV[2].y); vp[5] = h2u(rV[2].z, rV[2].w); \
        vp[6] = h2u(rV[3].x, rV[3].y); vp[7] = h2u(rV[3].z, rV[3].w); \
        unsigned* pp = &Ps[buf][prow * PH + pc4]; \
        *(uint4*)&pp[0] = rP[0]; \
        *(uint4*)&pp[4] = rP[1]; }

    AV_LOAD(0);
    AV_STORE(0);
    __syncthreads();

    int buf = 0;
    for (int c = 0; c < NPIX / 32; c++) {
        const bool more = (c + 1 < NPIX / 32);
        if (more) { const int ktn = (c + 1) * 32; AV_LOAD(ktn); }

        #pragma unroll
        for (int ks = 0; ks < 2; ks++) {
            const int k0h = ks * 8;                       // 16 keys = 8 half2
            unsigned a[2][4], b[8][2];
            #pragma unroll
            for (int mf = 0; mf < 2; mf++) {
                int mr = m_off + mf * 16 + g;
                a[mf][0] = Vs[buf][mr * PH + k0h + tig];
                a[mf][1] = Vs[buf][(mr + 8) * PH + k0h + tig];
                a[mf][2] = Vs[buf][mr * PH + k0h + tig + 4];
                a[mf][3] = Vs[buf][(mr + 8) * PH + k0h + tig + 4];
            }
            #pragma unroll
            for (int nf = 0; nf < 8; nf++) {
                int nc = n_off + nf * 8 + g;
                b[nf][0] = Ps[buf][nc * PH + k0h + tig];
                b[nf][1] = Ps[buf][nc * PH + k0h + tig + 4];
            }
            #pragma unroll
            for (int mf = 0; mf < 2; mf++)
                #pragma unroll
                for (int nf = 0; nf < 8; nf++)
                    mma16h(acc[mf][nf], a[mf], b[nf]);
        }
        if (more) AV_STORE(buf ^ 1);
        __syncthreads();
        buf ^= 1;
    }

    const float gm = gmp[0];
    #pragma unroll
    for (int mf = 0; mf < 2; mf++) {
        int r0 = m0 + m_off + mf * 16 + g;
        int r1 = r0 + 8;
        #pragma unroll
        for (int nf = 0; nf < 8; nf++) {
            int col = n0 + n_off + nf * 8 + 2 * tig;
            float2 x0 = *(const float2*)&xq[r0 * NPIX + col];
            float2 x1 = *(const float2*)&xq[r1 * NPIX + col];
            *(float2*)&out[r0 * NPIX + col] =
                make_float2(gm * acc[mf][nf][0] + x0.x, gm * acc[mf][nf][1] + x0.y);
            *(float2*)&out[r1 * NPIX + col] =
                make_float2(gm * acc[mf][nf][2] + x1.x, gm * acc[mf][nf][3] + x1.y);
        }
    }
}

// ---------------------------------------------------------------------------
extern "C" void kernel_launch(void* const* d_in, const int* in_sizes, int n_in,
                              void* d_out, int out_size)
{
    const float* x1    = (const float*)d_in[0];
    const float* x2    = (const float*)d_in[1];
    const float* sx1_w = (const float*)d_in[2];
    const float* sy1_w = (const float*)d_in[3];
    const float* bn1x  = (const float*)d_in[4];
    const float* bn1y  = (const float*)d_in[5];
    const float* sx2_w = (const float*)d_in[6];
    const float* sy2_w = (const float*)d_in[7];
    const float* bn2x  = (const float*)d_in[8];
    const float* bn2y  = (const float*)d_in[9];
    const float* q1_w  = (const float*)d_in[10];
    const float* q1_b  = (const float*)d_in[11];
    const float* k1_w  = (const float*)d_in[12];
    const float* k1_b  = (const float*)d_in[13];
    const float* v1_w  = (const float*)d_in[14];
    const float* v1_b  = (const float*)d_in[15];
    const float* q2_w  = (const float*)d_in[16];
    const float* q2_b  = (const float*)d_in[17];
    const float* k2_w  = (const float*)d_in[18];
    const float* k2_b  = (const float*)d_in[19];
    const float* v2_w  = (const float*)d_in[20];
    const float* v2_b  = (const float*)d_in[21];
    const float* gamma1 = (const float*)d_in[22];
    const float* gamma2 = (const float*)d_in[23];
    float* out = (float*)d_out;

    float *xf1, *xf2, *qb1, *kb1, *vb1, *qb2, *kb2, *vb2, *attn1, *attn2;
    float *wx1p, *wy1p, *wx2p, *wy2p;
    __half *p1, *p2;
    cudaGetSymbolAddress((void**)&xf1, g_xf1);
    cudaGetSymbolAddress((void**)&xf2, g_xf2);
    cudaGetSymbolAddress((void**)&qb1, g_qb1);
    cudaGetSymbolAddress((void**)&kb1, g_kb1);
    cudaGetSymbolAddress((void**)&vb1, g_vb1);
    cudaGetSymbolAddress((void**)&qb2, g_qb2);
    cudaGetSymbolAddress((void**)&kb2, g_kb2);
    cudaGetSymbolAddress((void**)&vb2, g_vb2);
    cudaGetSymbolAddress((void**)&attn1, g_attn1);
    cudaGetSymbolAddress((void**)&attn2, g_attn2);
    cudaGetSymbolAddress((void**)&p1, g_p1);
    cudaGetSymbolAddress((void**)&p2, g_p2);
    cudaGetSymbolAddress((void**)&wx1p, g_wx1p);
    cudaGetSymbolAddress((void**)&wy1p, g_wy1p);
    cudaGetSymbolAddress((void**)&wx2p, g_wx2p);
    cudaGetSymbolAddress((void**)&wy2p, g_wy2p);

    const int SOBEL_SMEM = (4 * 64 * PA + 2 * 32 * PB) * 4;
    const int PROJ_SMEM  = (2 * 64 * PA + 2 * 32 * PB) * 4;
    cudaFuncSetAttribute(sobel_mma, cudaFuncAttributeMaxDynamicSharedMemorySize, SOBEL_SMEM);
    cudaFuncSetAttribute(proj_mma,  cudaFuncAttributeMaxDynamicSharedMemorySize, PROJ_SMEM);

    dim3 blk(256);

    pack_all<<<dim3(CC * KW / 256, 4), blk>>>(sx1_w, sy1_w, sx2_w, sy2_w,
                                              wx1p, wy1p, wx2p, wy2p);

    sobel_mma<<<dim3(32, 4, 2), blk, SOBEL_SMEM>>>(
        x1, wx1p, wy1p, bn1x, bn1y, xf1,
        x2, wx2p, wy2p, bn2x, bn2y, xf2);

    ProjArgs qk;
    qk.A[0] = q1_w;  qk.B[0] = x1;  qk.bias[0] = q1_b; qk.out[0] = qb1;
    qk.A[1] = k1_w;  qk.B[1] = xf2; qk.bias[1] = k1_b; qk.out[1] = kb1;
    qk.A[2] = q2_w;  qk.B[2] = x2;  qk.bias[2] = q2_b; qk.out[2] = qb2;
    qk.A[3] = k2_w;  qk.B[3] = xf1; qk.bias[3] = k2_b; qk.out[3] = kb2;
    qk.M = CQ;
    proj_mma<<<dim3(32, 1, 4), blk, PROJ_SMEM>>>(qk);

    ProjArgs vv;
    vv.A[0] = v1_w;  vv.B[0] = xf2; vv.bias[0] = v1_b; vv.out[0] = vb1;
    vv.A[1] = v2_w;  vv.B[1] = xf1; vv.bias[1] = v2_b; vv.out[1] = vb2;
    vv.A[2] = v1_w;  vv.B[2] = xf2; vv.bias[2] = v1_b; vv.out[2] = vb1;
    vv.A[3] = v1_w;  vv.B[3] = xf2; vv.bias[3] = v1_b; vv.out[3] = vb1;
    vv.M = CC;
    proj_mma<<<dim3(32, 4, 2), blk, PROJ_SMEM>>>(vv);

    energy_mma<<<dim3(32, 64, 2), blk>>>(qb1, kb1, attn1, qb2, kb2, attn2);
    softmax_kernel<<<dim3(NPIX, 2), blk>>>(attn1, attn2, p1, p2);
    av_fp16<<<dim3(32, 2, 2), blk>>>(vb1, p1, x1, gamma1,
                                     vb2, p2, x2, gamma2, out);
}

// round 7
// speedup vs baseline: 1.3637x; 1.3637x over previous
#include <cuda_runtime.h>
#include <cuda_fp16.h>
#include <math.h>

#define CC   256
#define CQ   32
#define NPIX 4096
#define EPSB 1e-5f
#define KW   2304          // 9*256 conv K

#define PH 20              // half2 tile pad: [row][kh], 20 u32 row stride (16 used)

// ---------------- scratch ----------------
__device__ float g_xf1[CC * NPIX];
__device__ float g_xf2[CC * NPIX];
__device__ float g_qb1[CQ * NPIX];
__device__ float g_kb1[CQ * NPIX];
__device__ float g_vb1[CC * NPIX];
__device__ float g_qb2[CQ * NPIX];
__device__ float g_kb2[CQ * NPIX];
__device__ float g_vb2[CC * NPIX];
__device__ float g_attn1[(size_t)NPIX * NPIX];
__device__ float g_attn2[(size_t)NPIX * NPIX];
__device__ __half g_p1[(size_t)NPIX * NPIX];
__device__ __half g_p2[(size_t)NPIX * NPIX];
__device__ __half g_wx1h[CC * KW];
__device__ __half g_wy1h[CC * KW];
__device__ __half g_wx2h[CC * KW];
__device__ __half g_wy2h[CC * KW];

// ---------------- fp16 mma helper ----------------
__device__ __forceinline__ void mma16h(float* c, const unsigned* a, const unsigned* b) {
    asm volatile(
        "mma.sync.aligned.m16n8k16.row.col.f32.f16.f16.f32 "
        "{%0,%1,%2,%3}, {%4,%5,%6,%7}, {%8,%9}, {%0,%1,%2,%3};"
        : "+f"(c[0]), "+f"(c[1]), "+f"(c[2]), "+f"(c[3])
        : "r"(a[0]), "r"(a[1]), "r"(a[2]), "r"(a[3]), "r"(b[0]), "r"(b[1]));
}
__device__ __forceinline__ unsigned h2u(float lo, float hi) {
    __half2 h = __floats2half2_rn(lo, hi);
    return *reinterpret_cast<unsigned*>(&h);
}

// ---------------------------------------------------------------------------
// pack all 4 conv-weight tensors to fp16: w[m][ci][tap] -> wh[m][tap*256+ci]
// ---------------------------------------------------------------------------
__global__ void pack_all(const float* __restrict__ s0, const float* __restrict__ s1,
                         const float* __restrict__ s2, const float* __restrict__ s3,
                         __half* __restrict__ d0, __half* __restrict__ d1,
                         __half* __restrict__ d2, __half* __restrict__ d3)
{
    const int y = blockIdx.y;
    const float* s = (y == 0) ? s0 : (y == 1) ? s1 : (y == 2) ? s2 : s3;
    __half* d = (y == 0) ? d0 : (y == 1) ? d1 : (y == 2) ? d2 : d3;
    int t = blockIdx.x * 256 + threadIdx.x;
    int m = t / KW, r = t % KW;
    d[t] = __float2half(s[m * KW + (r & 255) * 9 + (r >> 8)]);
}

// ---------------------------------------------------------------------------
// Sobel fp16 (batched z=2): dual conv3x3 GEMM + BN + magnitude.
// m-tile 64, n-tile 128, k-chunk 32. grid (32, 4, 2), block 256 (2x4 warps).
// A: [m][kh] half2 smem (uint4 copy from prepacked fp16 weights).
// B: [n][kh] half2 smem (transposed image, cvt on the fly). Double-buffered.
// ---------------------------------------------------------------------------
__global__ void __launch_bounds__(256, 2) sobel_fp16(
    const float* __restrict__ x1a, const __half* __restrict__ wx1,
    const __half* __restrict__ wy1, const float* __restrict__ bn1x,
    const float* __restrict__ bn1y, float* __restrict__ o1,
    const float* __restrict__ x2a, const __half* __restrict__ wx2,
    const __half* __restrict__ wy2, const float* __restrict__ bn2x,
    const float* __restrict__ bn2y, float* __restrict__ o2)
{
    __shared__ unsigned Ax[2][64 * PH];
    __shared__ unsigned Ay[2][64 * PH];
    __shared__ unsigned Bt[2][128 * PH];

    const int z = blockIdx.z;
    const float* x   = z ? x2a : x1a;
    const __half* wxh = z ? wx2 : wx1;
    const __half* wyh = z ? wy2 : wy1;
    const float* bnx = z ? bn2x : bn1x;
    const float* bny = z ? bn2y : bn1y;
    float* out = z ? o2 : o1;

    const int tid = threadIdx.x;
    const int lane = tid & 31, wid = tid >> 5;
    const int g = lane >> 2, tig = lane & 3;
    const int m_off = (wid >> 2) * 32, n_off = (wid & 3) * 32;
    const int m0 = blockIdx.y * 64, n0 = blockIdx.x * 128;

    float accx[2][4][4] = {};
    float accy[2][4][4] = {};

    // A copy: thread -> (row am, 4 half2 cells at ak*4)
    const int am = tid >> 2, ak = tid & 3;
    // B: thread -> col n, 8 kh cells starting khb
    const int bn = tid & 127, khb = (tid >> 7) * 8;
    const int pix = n0 + bn;
    const int py = pix >> 6, px = pix & 63;

    uint4 rAx, rAy;
    unsigned rB[8];

    #define SB_LOAD(kt) { \
        rAx = *(const uint4*)&wxh[(m0 + am) * KW + (kt) + ak * 8]; \
        rAy = *(const uint4*)&wyh[(m0 + am) * KW + (kt) + ak * 8]; \
        const int tap = (kt) >> 8; \
        const int dy = tap / 3 - 1, dx = tap % 3 - 1; \
        const int cibase = (kt) & 255; \
        const int yy = py + dy, xx = px + dx; \
        const bool ok = (yy >= 0) && (yy < 64) && (xx >= 0) && (xx < 64); \
        const float* xp = x + yy * 64 + xx; \
        _Pragma("unroll") \
        for (int i = 0; i < 8; i++) { \
            int ci = cibase + 2 * (khb + i); \
            float f0 = ok ? xp[ci * NPIX] : 0.f; \
            float f1 = ok ? xp[(ci + 1) * NPIX] : 0.f; \
            rB[i] = h2u(f0, f1); \
        } }

    #define SB_STORE(buf) { \
        *(uint4*)&Ax[buf][am * PH + ak * 4] = rAx; \
        *(uint4*)&Ay[buf][am * PH + ak * 4] = rAy; \
        *(uint4*)&Bt[buf][bn * PH + khb] = make_uint4(rB[0], rB[1], rB[2], rB[3]); \
        *(uint4*)&Bt[buf][bn * PH + khb + 4] = make_uint4(rB[4], rB[5], rB[6], rB[7]); }

    SB_LOAD(0);
    SB_STORE(0);
    __syncthreads();

    int buf = 0;
    for (int c = 0; c < KW / 32; c++) {
        const bool more = (c + 1 < KW / 32);
        if (more) { const int ktn = (c + 1) * 32; SB_LOAD(ktn); }

        #pragma unroll
        for (int ks = 0; ks < 2; ks++) {
            const int k0h = ks * 8;
            unsigned ax[2][4], ay[2][4], b[4][2];
            #pragma unroll
            for (int mf = 0; mf < 2; mf++) {
                int mr = m_off + mf * 16 + g;
                ax[mf][0] = Ax[buf][mr * PH + k0h + tig];
                ax[mf][1] = Ax[buf][(mr + 8) * PH + k0h + tig];
                ax[mf][2] = Ax[buf][mr * PH + k0h + tig + 4];
                ax[mf][3] = Ax[buf][(mr + 8) * PH + k0h + tig + 4];
                ay[mf][0] = Ay[buf][mr * PH + k0h + tig];
                ay[mf][1] = Ay[buf][(mr + 8) * PH + k0h + tig];
                ay[mf][2] = Ay[buf][mr * PH + k0h + tig + 4];
                ay[mf][3] = Ay[buf][(mr + 8) * PH + k0h + tig + 4];
            }
            #pragma unroll
            for (int nf = 0; nf < 4; nf++) {
                int nc = n_off + nf * 8 + g;
                b[nf][0] = Bt[buf][nc * PH + k0h + tig];
                b[nf][1] = Bt[buf][nc * PH + k0h + tig + 4];
            }
            #pragma unroll
            for (int mf = 0; mf < 2; mf++)
                #pragma unroll
                for (int nf = 0; nf < 4; nf++) {
                    mma16h(accx[mf][nf], ax[mf], b[nf]);
                    mma16h(accy[mf][nf], ay[mf], b[nf]);
                }
        }
        if (more) SB_STORE(buf ^ 1);
        __syncthreads();
        buf ^= 1;
    }

    #pragma unroll
    for (int mf = 0; mf < 2; mf++) {
        int r0 = m0 + m_off + mf * 16 + g;
        int r1 = r0 + 8;
        float ivx0 = bnx[r0] * rsqrtf(bnx[768 + r0] + EPSB);
        float ivx1 = bnx[r1] * rsqrtf(bnx[768 + r1] + EPSB);
        float bx0 = bnx[256 + r0], bx1 = bnx[256 + r1];
        float mx0 = bnx[512 + r0], mx1 = bnx[512 + r1];
        float ivy0 = bny[r0] * rsqrtf(bny[768 + r0] + EPSB);
        float ivy1 = bny[r1] * rsqrtf(bny[768 + r1] + EPSB);
        float by0 = bny[256 + r0], by1 = bny[256 + r1];
        float my0 = bny[512 + r0], my1 = bny[512 + r1];
        #pragma unroll
        for (int nf = 0; nf < 4; nf++) {
            int col = n0 + n_off + nf * 8 + 2 * tig;
            float gx, gy;
            float2 o0, o1;
            gx = (accx[mf][nf][0] - mx0) * ivx0 + bx0;
            gy = (accy[mf][nf][0] - my0) * ivy0 + by0;
            o0.x = sqrtf(gx * gx + gy * gy);
            gx = (accx[mf][nf][1] - mx0) * ivx0 + bx0;
            gy = (accy[mf][nf][1] - my0) * ivy0 + by0;
            o0.y = sqrtf(gx * gx + gy * gy);
            gx = (accx[mf][nf][2] - mx1) * ivx1 + bx1;
            gy = (accy[mf][nf][2] - my1) * ivy1 + by1;
            o1.x = sqrtf(gx * gx + gy * gy);
            gx = (accx[mf][nf][3] - mx1) * ivx1 + bx1;
            gy = (accy[mf][nf][3] - my1) * ivy1 + by1;
            o1.y = sqrtf(gx * gx + gy * gy);
            *(float2*)&out[r0 * NPIX + col] = o0;
            *(float2*)&out[r1 * NPIX + col] = o1;
        }
    }
}

// ---------------------------------------------------------------------------
// proj fp16 (batched): out[M][4096] = W[M][256] * B + bias.
// grid (32, ceil(M/64), nz), block 256. Double-buffered, k-chunk 32.
// ---------------------------------------------------------------------------
struct ProjArgs {
    const float* A[4];
    const float* B[4];
    const float* bias[4];
    float* out[4];
    int M;
};

__global__ void __launch_bounds__(256, 2) proj_fp16(ProjArgs args)
{
    __shared__ unsigned As[2][64 * PH];
    __shared__ unsigned Bt[2][128 * PH];

    const int z = blockIdx.z;
    const float* A = args.A[z];
    const float* B = args.B[z];
    const float* bias = args.bias[z];
    float* out = args.out[z];
    const int M = args.M;

    const int tid = threadIdx.x;
    const int lane = tid & 31, wid = tid >> 5;
    const int g = lane >> 2, tig = lane & 3;
    const int m_off = (wid >> 2) * 32, n_off = (wid & 3) * 32;
    const int m0 = blockIdx.y * 64, n0 = blockIdx.x * 128;

    float acc[2][4][4] = {};

    const int am = tid >> 2, ak = tid & 3;
    const int bn = tid & 127, khb = (tid >> 7) * 8;

    unsigned rA[4], rB[8];

    #define PJ_LOAD(kt) { \
        if (m0 + am < M) { \
            float4 a0 = *(const float4*)&A[(m0 + am) * 256 + (kt) + ak * 8]; \
            float4 a1 = *(const float4*)&A[(m0 + am) * 256 + (kt) + ak * 8 + 4]; \
            rA[0] = h2u(a0.x, a0.y); rA[1] = h2u(a0.z, a0.w); \
            rA[2] = h2u(a1.x, a1.y); rA[3] = h2u(a1.z, a1.w); \
        } else { rA[0] = rA[1] = rA[2] = rA[3] = 0u; } \
        const float* bp = B + n0 + bn; \
        _Pragma("unroll") \
        for (int i = 0; i < 8; i++) { \
            int k = (kt) + 2 * (khb + i); \
            rB[i] = h2u(bp[(size_t)k * NPIX], bp[(size_t)(k + 1) * NPIX]); \
        } }

    #define PJ_STORE(buf) { \
        *(uint4*)&As[buf][am * PH + ak * 4] = make_uint4(rA[0], rA[1], rA[2], rA[3]); \
        *(uint4*)&Bt[buf][bn * PH + khb] = make_uint4(rB[0], rB[1], rB[2], rB[3]); \
        *(uint4*)&Bt[buf][bn * PH + khb + 4] = make_uint4(rB[4], rB[5], rB[6], rB[7]); }

    PJ_LOAD(0);
    PJ_STORE(0);
    __syncthreads();

    int buf = 0;
    for (int c = 0; c < 8; c++) {
        const bool more = (c + 1 < 8);
        if (more) { const int ktn = (c + 1) * 32; PJ_LOAD(ktn); }

        #pragma unroll
        for (int ks = 0; ks < 2; ks++) {
            const int k0h = ks * 8;
            unsigned a[2][4], b[4][2];
            #pragma unroll
            for (int mf = 0; mf < 2; mf++) {
                int mr = m_off + mf * 16 + g;
                a[mf][0] = As[buf][mr * PH + k0h + tig];
                a[mf][1] = As[buf][(mr + 8) * PH + k0h + tig];
                a[mf][2] = As[buf][mr * PH + k0h + tig + 4];
                a[mf][3] = As[buf][(mr + 8) * PH + k0h + tig + 4];
            }
            #pragma unroll
            for (int nf = 0; nf < 4; nf++) {
                int nc = n_off + nf * 8 + g;
                b[nf][0] = Bt[buf][nc * PH + k0h + tig];
                b[nf][1] = Bt[buf][nc * PH + k0h + tig + 4];
            }
            #pragma unroll
            for (int mf = 0; mf < 2; mf++)
                #pragma unroll
                for (int nf = 0; nf < 4; nf++)
                    mma16h(acc[mf][nf], a[mf], b[nf]);
        }
        if (more) PJ_STORE(buf ^ 1);
        __syncthreads();
        buf ^= 1;
    }

    #pragma unroll
    for (int mf = 0; mf < 2; mf++) {
        int r0 = m0 + m_off + mf * 16 + g;
        int r1 = r0 + 8;
        float b0 = (r0 < M) ? bias[r0] : 0.f;
        float b1 = (r1 < M) ? bias[r1] : 0.f;
        #pragma unroll
        for (int nf = 0; nf < 4; nf++) {
            int col = n0 + n_off + nf * 8 + 2 * tig;
            if (r0 < M)
                *(float2*)&out[r0 * NPIX + col] =
                    make_float2(acc[mf][nf][0] + b0, acc[mf][nf][1] + b0);
            if (r1 < M)
                *(float2*)&out[r1 * NPIX + col] =
                    make_float2(acc[mf][nf][2] + b1, acc[mf][nf][3] + b1);
        }
    }
}

// ---------------------------------------------------------------------------
// energy fp16 (batched z=2): e[m][n] = sum_{c<32} q[c][m]*k[c][n].
// grid (32, 64, 2), block 256. Single K chunk.
// ---------------------------------------------------------------------------
__global__ void energy_fp16(const float* __restrict__ q1, const float* __restrict__ k1,
                            float* __restrict__ e1,
                            const float* __restrict__ q2, const float* __restrict__ k2,
                            float* __restrict__ e2)
{
    __shared__ unsigned Qh[64 * PH];
    __shared__ unsigned Kh[128 * PH];

    const int z = blockIdx.z;
    const float* q = z ? q2 : q1;
    const float* k = z ? k2 : k1;
    float* e = z ? e2 : e1;

    const int tid = threadIdx.x;
    const int lane = tid & 31, wid = tid >> 5;
    const int g = lane >> 2, tig = lane & 3;
    const int m_off = (wid >> 2) * 32, n_off = (wid & 3) * 32;
    const int m0 = blockIdx.y * 64, n0 = blockIdx.x * 128;

    // Q: [c][m] global -> [m][kh] smem (A row-major)
    {
        const int am = tid >> 2, ak = tid & 3;
        const float* qp = q + m0 + am;
        unsigned r[4];
        #pragma unroll
        for (int i = 0; i < 4; i++) {
            int c = 2 * (ak * 4 + i);
            r[i] = h2u(qp[c * NPIX], qp[(c + 1) * NPIX]);
        }
        *(uint4*)&Qh[am * PH + ak * 4] = make_uint4(r[0], r[1], r[2], r[3]);
    }
    // K: [c][n] global -> [n][kh] smem (B col-major along k)
    {
        const int bn = tid & 127, khb = (tid >> 7) * 8;
        const float* kp = k + n0 + bn;
        unsigned r[8];
        #pragma unroll
        for (int i = 0; i < 8; i++) {
            int c = 2 * (khb + i);
            r[i] = h2u(kp[c * NPIX], kp[(c + 1) * NPIX]);
        }
        *(uint4*)&Kh[bn * PH + khb] = make_uint4(r[0], r[1], r[2], r[3]);
        *(uint4*)&Kh[bn * PH + khb + 4] = make_uint4(r[4], r[5], r[6], r[7]);
    }
    __syncthreads();

    float acc[2][4][4] = {};
    #pragma unroll
    for (int ks = 0; ks < 2; ks++) {
        const int k0h = ks * 8;
        unsigned a[2][4], b[4][2];
        #pragma unroll
        for (int mf = 0; mf < 2; mf++) {
            int mr = m_off + mf * 16 + g;
            a[mf][0] = Qh[mr * PH + k0h + tig];
            a[mf][1] = Qh[(mr + 8) * PH + k0h + tig];
            a[mf][2] = Qh[mr * PH + k0h + tig + 4];
            a[mf][3] = Qh[(mr + 8) * PH + k0h + tig + 4];
        }
        #pragma unroll
        for (int nf = 0; nf < 4; nf++) {
            int nc = n_off + nf * 8 + g;
            b[nf][0] = Kh[nc * PH + k0h + tig];
            b[nf][1] = Kh[nc * PH + k0h + tig + 4];
        }
        #pragma unroll
        for (int mf = 0; mf < 2; mf++)
            #pragma unroll
            for (int nf = 0; nf < 4; nf++)
                mma16h(acc[mf][nf], a[mf], b[nf]);
    }

    #pragma unroll
    for (int mf = 0; mf < 2; mf++) {
        int r0 = m0 + m_off + mf * 16 + g;
        int r1 = r0 + 8;
        #pragma unroll
        for (int nf = 0; nf < 4; nf++) {
            int col = n0 + n_off + nf * 8 + 2 * tig;
            *(float2*)&e[(size_t)r0 * NPIX + col] = make_float2(acc[mf][nf][0], acc[mf][nf][1]);
            *(float2*)&e[(size_t)r1 * NPIX + col] = make_float2(acc[mf][nf][2], acc[mf][nf][3]);
        }
    }
}

// ---------------------------------------------------------------------------
// softmax (batched z=2): read fp32 E rows, write normalized fp16 P rows.
// ---------------------------------------------------------------------------
__global__ void softmax_kernel(const float* __restrict__ e1, const float* __restrict__ e2,
                               __half* __restrict__ p1, __half* __restrict__ p2)
{
    __shared__ float red[8];
    const float* e = blockIdx.y ? e2 : e1;
    __half* po = blockIdx.y ? p2 : p1;
    const float4* p = (const float4*)(e + (size_t)blockIdx.x * NPIX);
    __half2* ph = (__half2*)(po + (size_t)blockIdx.x * NPIX);
    const int tid = threadIdx.x;
    float4 v[4];
    float mx = -1e30f;
    #pragma unroll
    for (int r = 0; r < 4; r++) {
        v[r] = p[tid + r * 256];
        mx = fmaxf(mx, fmaxf(fmaxf(v[r].x, v[r].y), fmaxf(v[r].z, v[r].w)));
    }
    #pragma unroll
    for (int o = 16; o > 0; o >>= 1)
        mx = fmaxf(mx, __shfl_xor_sync(0xffffffffu, mx, o));
    if ((tid & 31) == 0) red[tid >> 5] = mx;
    __syncthreads();
    mx = red[0];
    #pragma unroll
    for (int w = 1; w < 8; w++) mx = fmaxf(mx, red[w]);
    __syncthreads();

    float s = 0.f;
    #pragma unroll
    for (int r = 0; r < 4; r++) {
        v[r].x = __expf(v[r].x - mx); s += v[r].x;
        v[r].y = __expf(v[r].y - mx); s += v[r].y;
        v[r].z = __expf(v[r].z - mx); s += v[r].z;
        v[r].w = __expf(v[r].w - mx); s += v[r].w;
    }
    #pragma unroll
    for (int o = 16; o > 0; o >>= 1)
        s += __shfl_xor_sync(0xffffffffu, s, o);
    if ((tid & 31) == 0) red[tid >> 5] = s;
    __syncthreads();
    s = 0.f;
    #pragma unroll
    for (int w = 0; w < 8; w++) s += red[w];
    const float inv = 1.f / s;
    #pragma unroll
    for (int r = 0; r < 4; r++) {
        int i2 = (tid + r * 256) * 2;
        ph[i2]     = __floats2half2_rn(v[r].x * inv, v[r].y * inv);
        ph[i2 + 1] = __floats2half2_rn(v[r].z * inv, v[r].w * inv);
    }
}

// ---------------------------------------------------------------------------
// av fp16 (batched z=2): out[m][n] = gamma * sum_k V[m][k] * P[n][k] + xq[m][n]
// m-tile 128, n-tile 128, k-tile 32. grid (32, 2, 2), block 256 (4x2 warps).
// ---------------------------------------------------------------------------
__global__ void __launch_bounds__(256, 2) av_fp16(
    const float* __restrict__ v1, const __half* __restrict__ p1,
    const float* __restrict__ xq1, const float* __restrict__ gm1,
    const float* __restrict__ v2, const __half* __restrict__ p2,
    const float* __restrict__ xq2, const float* __restrict__ gm2,
    float* __restrict__ outbase)
{
    __shared__ unsigned Vs[2][128 * PH];
    __shared__ unsigned Ps[2][128 * PH];

    const int z = blockIdx.z;
    const float* vmat = z ? v2 : v1;
    const __half* pm  = z ? p2 : p1;
    const float* xq   = z ? xq2 : xq1;
    const float* gmp  = z ? gm2 : gm1;
    float* out = outbase + (size_t)z * CC * NPIX;

    const int tid = threadIdx.x;
    const int lane = tid & 31, wid = tid >> 5;
    const int g = lane >> 2, tig = lane & 3;
    const int m_off = (wid >> 1) * 32;
    const int n_off = (wid & 1) * 64;
    const int m0 = blockIdx.y * 128, n0 = blockIdx.x * 128;

    float acc[2][8][4] = {};

    const int vrow = tid >> 1, vc8 = (tid & 1) * 16;
    const int prow = tid >> 1, pc4 = (tid & 1) * 8;

    float4 rV[4];
    uint4 rP[2];

    #define AV_LOAD(kt) { \
        _Pragma("unroll") \
        for (int r = 0; r < 4; r++) \
            rV[r] = *(const float4*)&vmat[(m0 + vrow) * NPIX + (kt) + vc8 + r * 4]; \
        const unsigned* pu = (const unsigned*)(pm + (size_t)(n0 + prow) * NPIX + (kt)); \
        rP[0] = *(const uint4*)&pu[pc4]; \
        rP[1] = *(const uint4*)&pu[pc4 + 4]; }

    #define AV_STORE(buf) { \
        unsigned* vp = &Vs[buf][vrow * PH + vc8 / 2]; \
        vp[0] = h2u(rV[0].x, rV[0].y); vp[1] = h2u(rV[0].z, rV[0].w); \
        vp[2] = h2u(rV[1].x, rV[1].y); vp[3] = h2u(rV[1].z, rV[1].w); \
        vp[4] = h2u(rV[2].x, rV[2].y); vp[5] = h2u(rV[2].z, rV[2].w); \
        vp[6] = h2u(rV[3].x, rV[3].y); vp[7] = h2u(rV[3].z, rV[3].w); \
        unsigned* pp = &Ps[buf][prow * PH + pc4]; \
        *(uint4*)&pp[0] = rP[0]; \
        *(uint4*)&pp[4] = rP[1]; }

    AV_LOAD(0);
    AV_STORE(0);
    __syncthreads();

    int buf = 0;
    for (int c = 0; c < NPIX / 32; c++) {
        const bool more = (c + 1 < NPIX / 32);
        if (more) { const int ktn = (c + 1) * 32; AV_LOAD(ktn); }

        #pragma unroll
        for (int ks = 0; ks < 2; ks++) {
            const int k0h = ks * 8;
            unsigned a[2][4], b[8][2];
            #pragma unroll
            for (int mf = 0; mf < 2; mf++) {
                int mr = m_off + mf * 16 + g;
                a[mf][0] = Vs[buf][mr * PH + k0h + tig];
                a[mf][1] = Vs[buf][(mr + 8) * PH + k0h + tig];
                a[mf][2] = Vs[buf][mr * PH + k0h + tig + 4];
                a[mf][3] = Vs[buf][(mr + 8) * PH + k0h + tig + 4];
            }
            #pragma unroll
            for (int nf = 0; nf < 8; nf++) {
                int nc = n_off + nf * 8 + g;
                b[nf][0] = Ps[buf][nc * PH + k0h + tig];
                b[nf][1] = Ps[buf][nc * PH + k0h + tig + 4];
            }
            #pragma unroll
            for (int mf = 0; mf < 2; mf++)
                #pragma unroll
                for (int nf = 0; nf < 8; nf++)
                    mma16h(acc[mf][nf], a[mf], b[nf]);
        }
        if (more) AV_STORE(buf ^ 1);
        __syncthreads();
        buf ^= 1;
    }

    const float gm = gmp[0];
    #pragma unroll
    for (int mf = 0; mf < 2; mf++) {
        int r0 = m0 + m_off + mf * 16 + g;
        int r1 = r0 + 8;
        #pragma unroll
        for (int nf = 0; nf < 8; nf++) {
            int col = n0 + n_off + nf * 8 + 2 * tig;
            float2 x0 = *(const float2*)&xq[r0 * NPIX + col];
            float2 x1 = *(const float2*)&xq[r1 * NPIX + col];
            *(float2*)&out[r0 * NPIX + col] =
                make_float2(gm * acc[mf][nf][0] + x0.x, gm * acc[mf][nf][1] + x0.y);
            *(float2*)&out[r1 * NPIX + col] =
                make_float2(gm * acc[mf][nf][2] + x1.x, gm * acc[mf][nf][3] + x1.y);
        }
    }
}

// ---------------------------------------------------------------------------
extern "C" void kernel_launch(void* const* d_in, const int* in_sizes, int n_in,
                              void* d_out, int out_size)
{
    const float* x1    = (const float*)d_in[0];
    const float* x2    = (const float*)d_in[1];
    const float* sx1_w = (const float*)d_in[2];
    const float* sy1_w = (const float*)d_in[3];
    const float* bn1x  = (const float*)d_in[4];
    const float* bn1y  = (const float*)d_in[5];
    const float* sx2_w = (const float*)d_in[6];
    const float* sy2_w = (const float*)d_in[7];
    const float* bn2x  = (const float*)d_in[8];
    const float* bn2y  = (const float*)d_in[9];
    const float* q1_w  = (const float*)d_in[10];
    const float* q1_b  = (const float*)d_in[11];
    const float* k1_w  = (const float*)d_in[12];
    const float* k1_b  = (const float*)d_in[13];
    const float* v1_w  = (const float*)d_in[14];
    const float* v1_b  = (const float*)d_in[15];
    const float* q2_w  = (const float*)d_in[16];
    const float* q2_b  = (const float*)d_in[17];
    const float* k2_w  = (const float*)d_in[18];
    const float* k2_b  = (const float*)d_in[19];
    const float* v2_w  = (const float*)d_in[20];
    const float* v2_b  = (const float*)d_in[21];
    const float* gamma1 = (const float*)d_in[22];
    const float* gamma2 = (const float*)d_in[23];
    float* out = (float*)d_out;

    float *xf1, *xf2, *qb1, *kb1, *vb1, *qb2, *kb2, *vb2, *attn1, *attn2;
    __half *wx1h, *wy1h, *wx2h, *wy2h, *p1, *p2;
    cudaGetSymbolAddress((void**)&xf1, g_xf1);
    cudaGetSymbolAddress((void**)&xf2, g_xf2);
    cudaGetSymbolAddress((void**)&qb1, g_qb1);
    cudaGetSymbolAddress((void**)&kb1, g_kb1);
    cudaGetSymbolAddress((void**)&vb1, g_vb1);
    cudaGetSymbolAddress((void**)&qb2, g_qb2);
    cudaGetSymbolAddress((void**)&kb2, g_kb2);
    cudaGetSymbolAddress((void**)&vb2, g_vb2);
    cudaGetSymbolAddress((void**)&attn1, g_attn1);
    cudaGetSymbolAddress((void**)&attn2, g_attn2);
    cudaGetSymbolAddress((void**)&p1, g_p1);
    cudaGetSymbolAddress((void**)&p2, g_p2);
    cudaGetSymbolAddress((void**)&wx1h, g_wx1h);
    cudaGetSymbolAddress((void**)&wy1h, g_wy1h);
    cudaGetSymbolAddress((void**)&wx2h, g_wx2h);
    cudaGetSymbolAddress((void**)&wy2h, g_wy2h);

    dim3 blk(256);

    pack_all<<<dim3(CC * KW / 256, 4), blk>>>(sx1_w, sy1_w, sx2_w, sy2_w,
                                              wx1h, wy1h, wx2h, wy2h);

    sobel_fp16<<<dim3(32, 4, 2), blk>>>(
        x1, wx1h, wy1h, bn1x, bn1y, xf1,
        x2, wx2h, wy2h, bn2x, bn2y, xf2);

    ProjArgs qk;
    qk.A[0] = q1_w;  qk.B[0] = x1;  qk.bias[0] = q1_b; qk.out[0] = qb1;
    qk.A[1] = k1_w;  qk.B[1] = xf2; qk.bias[1] = k1_b; qk.out[1] = kb1;
    qk.A[2] = q2_w;  qk.B[2] = x2;  qk.bias[2] = q2_b; qk.out[2] = qb2;
    qk.A[3] = k2_w;  qk.B[3] = xf1; qk.bias[3] = k2_b; qk.out[3] = kb2;
    qk.M = CQ;
    proj_fp16<<<dim3(32, 1, 4), blk>>>(qk);

    ProjArgs vv;
    vv.A[0] = v1_w;  vv.B[0] = xf2; vv.bias[0] = v1_b; vv.out[0] = vb1;
    vv.A[1] = v2_w;  vv.B[1] = xf1; vv.bias[1] = v2_b; vv.out[1] = vb2;
    vv.A[2] = v1_w;  vv.B[2] = xf2; vv.bias[2] = v1_b; vv.out[2] = vb1;
    vv.A[3] = v1_w;  vv.B[3] = xf2; vv.bias[3] = v1_b; vv.out[3] = vb1;
    vv.M = CC;
    proj_fp16<<<dim3(32, 4, 2), blk>>>(vv);

    energy_fp16<<<dim3(32, 64, 2), blk>>>(qb1, kb1, attn1, qb2, kb2, attn2);
    softmax_kernel<<<dim3(NPIX, 2), blk>>>(attn1, attn2, p1, p2);
    av_fp16<<<dim3(32, 2, 2), blk>>>(vb1, p1, x1, gamma1,
                                     vb2, p2, x2, gamma2, out);
}